// round 12
// baseline (speedup 1.0000x reference)
#include <cuda_runtime.h>
#include <cuda_bf16.h>
#include <cstdint>
#include <math.h>

#define NPTS 50000
#define KNB  16
#define HALF 64
#define DIM  128
#define TILES16 (NPTS / 16)      // 3125 tiles of 16 points
#define RS    272                // smem row stride bytes (136 bf16: 128 + 8 pad)

// ---------------- scratch (__device__ globals; no allocs allowed) -------
__device__ float g_p0[NPTS * HALF];
__device__ float g_p1[NPTS * HALF];
__device__ float g_u [NPTS * DIM];   // p1 @ W3a_top
__device__ float g_cc[NPTS * DIM];   // b3a - u + p_local @ W3a_bot

// ---------------- k_mlp smem map (bytes) ----------------
#define OFF_WB_HI 0
#define OFF_WB_LO 34816
#define OFF_BB    69632
#define SMEM_BYTES 70144

#define UC_SMEM_BYTES 75264

// ---------------- helpers ----------------
static __device__ __forceinline__ uint32_t smem_to_u32(const void* p) {
    uint32_t a;
    asm("{ .reg .u64 t; cvta.to.shared.u64 t, %1; cvt.u32.u64 %0, t; }" : "=r"(a) : "l"(p));
    return a;
}
static __device__ __forceinline__ void ldsm_x4(uint32_t* r, uint32_t addr) {
    asm volatile("ldmatrix.sync.aligned.m8n8.x4.shared.b16 {%0,%1,%2,%3}, [%4];"
        : "=r"(r[0]), "=r"(r[1]), "=r"(r[2]), "=r"(r[3]) : "r"(addr));
}
static __device__ __forceinline__ void mma16816(float* d, const uint32_t* a, const uint32_t* b) {
    asm volatile("mma.sync.aligned.m16n8k16.row.col.f32.bf16.bf16.f32 "
        "{%0,%1,%2,%3}, {%4,%5,%6,%7}, {%8,%9}, {%0,%1,%2,%3};"
        : "+f"(d[0]), "+f"(d[1]), "+f"(d[2]), "+f"(d[3])
        : "r"(a[0]), "r"(a[1]), "r"(a[2]), "r"(a[3]), "r"(b[0]), "r"(b[1]));
}
// branch-free gelu via A&S 7.1.26 erfc (|eps| <= 1.5e-7), 2 MUFU
static __device__ __forceinline__ float gelu_fast(float x) {
    const float za = fabsf(x) * 0.70710678118654752f;
    float den = fmaf(za, 0.3275911f, 1.0f);
    float t;
    asm("rcp.approx.f32 %0, %1;" : "=f"(t) : "f"(den));
    float q = t * fmaf(t, fmaf(t, fmaf(t, fmaf(t, 0.5307027145f, -0.7265760135f),
                                       0.7107068705f), -0.142248368f), 0.127414796f);
    float ex;
    asm("ex2.approx.f32 %0, %1;" : "=f"(ex) : "f"(za * za * -1.442695041f));
    float E  = q * ex;
    float xe = x * E;
    return (x >= 0.f) ? (x - xe) : xe;
}
static __device__ __forceinline__ uint32_t split_trunc2(float a, float b, float &ra, float &rb) {
    uint32_t ua = __float_as_uint(a) & 0xFFFF0000u;
    uint32_t ub = __float_as_uint(b) & 0xFFFF0000u;
    ra = a - __uint_as_float(ua);
    rb = b - __uint_as_float(ub);
    return __byte_perm(ua, ub, 0x7632);
}
static __device__ __forceinline__ uint32_t cvt_bf2(float a, float b) {   // x=a, y=b
    uint32_t r;
    asm("cvt.rn.bf16x2.f32 %0, %1, %2;" : "=r"(r) : "f"(b), "f"(a));
    return r;
}
static __device__ __forceinline__ uint32_t split_rn2(float a, float b, float &ra, float &rb) {
    __nv_bfloat16 ha = __float2bfloat16_rn(a), hb = __float2bfloat16_rn(b);
    ra = a - __bfloat162float(ha);
    rb = b - __bfloat162float(hb);
    __nv_bfloat162 p; p.x = ha; p.y = hb;
    return *(uint32_t*)&p;
}
static __host__ __device__ __forceinline__ int perm_pair(int k) {
    int b = k & ~15, r = k & 15;
    return b + ((r >> 2) << 1) + ((r & 2) << 2);
}

// ---------------- kernel 1: p0 = xyz@W1+b1 ; p1 = p0@W2+b2 ----------------
__global__ void __launch_bounds__(256)
k_p01(const float* __restrict__ xyz, const float* __restrict__ W1,
      const float* __restrict__ b1, const float* __restrict__ W2,
      const float* __restrict__ b2) {
    __shared__ float sp0[16][HALF];
    const int tid  = threadIdx.x;
    const int base = blockIdx.x * 16;

    for (int t = tid; t < 16 * HALF; t += 256) {
        int p = t >> 6, c = t & 63;
        int i = base + p;
        float x = __ldg(&xyz[i * 3 + 0]);
        float y = __ldg(&xyz[i * 3 + 1]);
        float z = __ldg(&xyz[i * 3 + 2]);
        float v = fmaf(z, __ldg(&W1[2 * HALF + c]), __ldg(&b1[c]));
        v = fmaf(y, __ldg(&W1[1 * HALF + c]), v);
        v = fmaf(x, __ldg(&W1[0 * HALF + c]), v);
        g_p0[i * HALF + c] = v;
        sp0[p][c] = v;
    }
    __syncthreads();

    const int c  = tid & 63;
    const int p0i = (tid >> 6) * 4;
    float bb = __ldg(&b2[c]);
    float a0 = bb, a1 = bb, a2 = bb, a3 = bb;
#pragma unroll 8
    for (int e = 0; e < HALF; e++) {
        float w = __ldg(&W2[e * HALF + c]);
        a0 = fmaf(sp0[p0i + 0][e], w, a0);
        a1 = fmaf(sp0[p0i + 1][e], w, a1);
        a2 = fmaf(sp0[p0i + 2][e], w, a2);
        a3 = fmaf(sp0[p0i + 3][e], w, a3);
    }
    g_p1[(base + p0i + 0) * HALF + c] = a0;
    g_p1[(base + p0i + 1) * HALF + c] = a1;
    g_p1[(base + p0i + 2) * HALF + c] = a2;
    g_p1[(base + p0i + 3) * HALF + c] = a3;
}

// ---------------- kernel 2: fused p_local + (u, cc) --------------------
__global__ void __launch_bounds__(256)
k_uc(const int* __restrict__ knn, const float* __restrict__ W3a,
     const float* __restrict__ b3a) {
    extern __shared__ float us[];
    float* sW   = us;              // 16384
    float* sp1  = us + 16384;      // 16 x 64
    float* spl  = sp1 + 1024;      // 16 x 64
    float* sb   = spl + 1024;      // 128
    int*   sknn = (int*)(sb + 128);// 256

    const int tid  = threadIdx.x;
    const int base = blockIdx.x * 16;

    for (int t = tid; t < 16384; t += 256) sW[t] = __ldg(&W3a[t]);
    if (tid < 128) sb[tid] = __ldg(&b3a[tid]);
    sknn[tid] = __ldg(&knn[base * KNB + tid]);
    for (int t = tid; t < 1024; t += 256) {
        int p = t >> 6, e = t & 63;
        sp1[t] = g_p1[(base + p) * HALF + e];
    }
    __syncthreads();

    for (int t = tid; t < 1024; t += 256) {
        int p = t >> 6, c = t & 63;
        float own = g_p0[(base + p) * HALF + c];
        float m = -3.402823466e38f;
#pragma unroll
        for (int k = 0; k < KNB; k++) {
            int j = sknn[p * KNB + k];
            m = fmaxf(m, __ldg(&g_p0[j * HALF + c]) - own);
        }
        spl[t] = m;
    }
    __syncthreads();

    const int c  = tid & 127;
    const int ph = (tid >> 7) * 8;
    float aU[8], aC[8];
#pragma unroll
    for (int pp = 0; pp < 8; pp++) { aU[pp] = 0.f; aC[pp] = sb[c]; }
#pragma unroll 8
    for (int e = 0; e < HALF; e++) {
        float w1 = sW[e * DIM + c];
        float w2 = sW[(HALF + e) * DIM + c];
#pragma unroll
        for (int pp = 0; pp < 8; pp++) {
            aU[pp] = fmaf(sp1[(ph + pp) * HALF + e], w1, aU[pp]);
            aC[pp] = fmaf(spl[(ph + pp) * HALF + e], w2, aC[pp]);
        }
    }
#pragma unroll
    for (int pp = 0; pp < 8; pp++) {
        size_t idx = (size_t)(base + ph + pp) * DIM + c;
        g_u[idx]  = aU[pp];
        g_cc[idx] = aC[pp] - aU[pp];
    }
}

// ---------------- kernel 3: 2 points/warp, B-frag reuse across 32 rows ---
// Warp owns two points (32 rows) x full 128 cols; each ldsm'd B fragment
// feeds 12 MMAs instead of 6, halving L1 ldsm bytes per output.
__global__ void __launch_bounds__(256, 1)
k_mlp(const int* __restrict__ knn,
      const float* __restrict__ W3b, const float* __restrict__ b3b,
      float* __restrict__ out) {
    extern __shared__ char smem[];
    const uint32_t sbase = smem_to_u32(smem);
    const int tid  = threadIdx.x;
    const int wid  = tid >> 5;
    const int lane = tid & 31;

    float* sBb = (float*)(smem + OFF_BB);

    // ---- load + split W3b: stored [n][perm(k)] = W[k][n], bf16 hi/lo ----
    for (int idx = tid; idx < 8192; idx += 256) {
        int n = idx >> 6, ep = idx & 63, k = ep << 1;
        uint32_t off = (uint32_t)n * RS + (uint32_t)perm_pair(k) * 2;
        float b0 = __ldg(&W3b[k * DIM + n]);
        float b1v = __ldg(&W3b[(k + 1) * DIM + n]);
        float rb0, rb1;
        *(uint32_t*)(smem + OFF_WB_HI + off) = split_rn2(b0, b1v, rb0, rb1);
        *(uint32_t*)(smem + OFF_WB_LO + off) = cvt_bf2(rb0, rb1);
    }
    if (tid < 128) sBb[tid] = __ldg(&b3b[tid]);
    __syncthreads();

    const int qr = lane >> 2;
    const int qc = (lane & 3) * 2;
    const int q4 = (lane & 3) * 4;
    const uint32_t bOff = ((uint32_t)(lane & 7) + ((uint32_t)(lane >> 4) & 1) * 8) * RS
                        + ((uint32_t)(lane >> 3) & 1) * 16;
    const uint32_t wHi = sbase + OFF_WB_HI + bOff;
    const uint32_t wLo = sbase + OFF_WB_LO + bOff;

    const int gstep = gridDim.x;
    int tile = blockIdx.x;
    if (tile >= TILES16) return;

    // ---- prologue: knn for both points in one 32-lane load ----
    // lane<16 -> point i0's 16 nbrs; lane>=16 -> point i1's
    int jj = __ldg(&knn[(tile * 16 + wid * 2 + (lane >> 4)) * KNB + (lane & 15)]);
    const float* u0; const float* u1; const float* u2; const float* u3;
    const float* c0; const float* c1;
    {
        const int ja = __shfl_sync(0xFFFFFFFF, jj, qr);
        const int jb = __shfl_sync(0xFFFFFFFF, jj, qr + 8);
        const int jc = __shfl_sync(0xFFFFFFFF, jj, qr + 16);
        const int jd = __shfl_sync(0xFFFFFFFF, jj, qr + 24);
        const int i0 = tile * 16 + wid * 2;
        u0 = g_u + (size_t)ja * DIM + q4;
        u1 = g_u + (size_t)jb * DIM + q4;
        u2 = g_u + (size_t)jc * DIM + q4;
        u3 = g_u + (size_t)jd * DIM + q4;
        c0 = g_cc + (size_t)i0 * DIM + q4;
        c1 = g_cc + (size_t)(i0 + 1) * DIM + q4;
    }
    float4 va = *(const float4*)(u0);
    float4 vb = *(const float4*)(u1);
    float4 vd = *(const float4*)(u2);
    float4 ve = *(const float4*)(u3);
    float4 vc0 = *(const float4*)(c0);
    float4 vc1 = *(const float4*)(c1);

    for (; tile < TILES16; tile += gstep) {
        const int i0 = tile * 16 + wid * 2;

        const int tnext = tile + gstep;
        int jjn = 0;
        if (tnext < TILES16)
            jjn = __ldg(&knn[(tnext * 16 + wid * 2 + (lane >> 4)) * KNB + (lane & 15)]);

        float acc0[16][4];   // point i0: 16 rows x 128 cols
        float acc1[16][4];   // point i0+1
#pragma unroll
        for (int t = 0; t < 16; t++) {
            acc0[t][0] = acc0[t][1] = acc0[t][2] = acc0[t][3] = 0.f;
            acc1[t][0] = acc1[t][1] = acc1[t][2] = acc1[t][3] = 0.f;
        }

#pragma unroll
        for (int ks = 0; ks < 8; ks++) {
            float4 na, nb, nd, ne, nc0, nc1;
            if (ks < 7) {
                const int kb = (ks + 1) * 16;
                na = *(const float4*)(u0 + kb);
                nb = *(const float4*)(u1 + kb);
                nd = *(const float4*)(u2 + kb);
                ne = *(const float4*)(u3 + kb);
                nc0 = *(const float4*)(c0 + kb);
                nc1 = *(const float4*)(c1 + kb);
            } else {
                const int ja = __shfl_sync(0xFFFFFFFF, jjn, qr);
                const int jb2 = __shfl_sync(0xFFFFFFFF, jjn, qr + 8);
                const int jc2 = __shfl_sync(0xFFFFFFFF, jjn, qr + 16);
                const int jd2 = __shfl_sync(0xFFFFFFFF, jjn, qr + 24);
                const int in0 = (tnext < TILES16) ? (tnext * 16 + wid * 2) : 0;
                u0 = g_u + (size_t)ja * DIM + q4;
                u1 = g_u + (size_t)jb2 * DIM + q4;
                u2 = g_u + (size_t)jc2 * DIM + q4;
                u3 = g_u + (size_t)jd2 * DIM + q4;
                c0 = g_cc + (size_t)in0 * DIM + q4;
                c1 = g_cc + (size_t)(in0 + 1) * DIM + q4;
                na = *(const float4*)(u0);
                nb = *(const float4*)(u1);
                nd = *(const float4*)(u2);
                ne = *(const float4*)(u3);
                nc0 = *(const float4*)(c0);
                nc1 = *(const float4*)(c1);
            }

            uint32_t aHi[8], aLo[8];
            {
                float r0, r1, r2, r3;
                // point 0, rows qr (va) and qr+8 (vb)
                float h00 = gelu_fast(va.x + vc0.x), h01 = gelu_fast(va.y + vc0.y);
                float h02 = gelu_fast(va.z + vc0.z), h03 = gelu_fast(va.w + vc0.w);
                float h10 = gelu_fast(vb.x + vc0.x), h11 = gelu_fast(vb.y + vc0.y);
                float h12 = gelu_fast(vb.z + vc0.z), h13 = gelu_fast(vb.w + vc0.w);
                aHi[0] = split_trunc2(h00, h01, r0, r1);
                aHi[2] = split_trunc2(h02, h03, r2, r3);
                aLo[0] = cvt_bf2(r0, r1);
                aLo[2] = cvt_bf2(r2, r3);
                aHi[1] = split_trunc2(h10, h11, r0, r1);
                aHi[3] = split_trunc2(h12, h13, r2, r3);
                aLo[1] = cvt_bf2(r0, r1);
                aLo[3] = cvt_bf2(r2, r3);
                // point 1, rows qr (vd) and qr+8 (ve)
                float h20 = gelu_fast(vd.x + vc1.x), h21 = gelu_fast(vd.y + vc1.y);
                float h22 = gelu_fast(vd.z + vc1.z), h23 = gelu_fast(vd.w + vc1.w);
                float h30 = gelu_fast(ve.x + vc1.x), h31 = gelu_fast(ve.y + vc1.y);
                float h32 = gelu_fast(ve.z + vc1.z), h33 = gelu_fast(ve.w + vc1.w);
                aHi[4] = split_trunc2(h20, h21, r0, r1);
                aHi[6] = split_trunc2(h22, h23, r2, r3);
                aLo[4] = cvt_bf2(r0, r1);
                aLo[6] = cvt_bf2(r2, r3);
                aHi[5] = split_trunc2(h30, h31, r0, r1);
                aHi[7] = split_trunc2(h32, h33, r2, r3);
                aLo[5] = cvt_bf2(r0, r1);
                aLo[7] = cvt_bf2(r2, r3);
            }

            const uint32_t ka = (uint32_t)ks * 32;
#pragma unroll
            for (int ntp = 0; ntp < 8; ntp++) {
                uint32_t bHi[4], bLo[4];
                ldsm_x4(bHi, wHi + (uint32_t)ntp * 16 * RS + ka);
                ldsm_x4(bLo, wLo + (uint32_t)ntp * 16 * RS + ka);
                // point 0
                mma16816(acc0[2 * ntp],     aHi,     bHi);
                mma16816(acc0[2 * ntp + 1], aHi,     bHi + 2);
                mma16816(acc0[2 * ntp],     aHi,     bLo);
                mma16816(acc0[2 * ntp + 1], aHi,     bLo + 2);
                mma16816(acc0[2 * ntp],     aLo,     bHi);
                mma16816(acc0[2 * ntp + 1], aLo,     bHi + 2);
                // point 1 (reuse same B fragments)
                mma16816(acc1[2 * ntp],     aHi + 4, bHi);
                mma16816(acc1[2 * ntp + 1], aHi + 4, bHi + 2);
                mma16816(acc1[2 * ntp],     aHi + 4, bLo);
                mma16816(acc1[2 * ntp + 1], aHi + 4, bLo + 2);
                mma16816(acc1[2 * ntp],     aLo + 4, bHi);
                mma16816(acc1[2 * ntp + 1], aLo + 4, bHi + 2);
            }
            va = na; vb = nb; vd = nd; ve = ne; vc0 = nc0; vc1 = nc1;
        }

        // ---- epilogue: +b3b, store both points ----
        {
            float* ob0 = out + ((size_t)i0 * KNB) * DIM;
            float* ob1 = out + ((size_t)(i0 + 1) * KNB) * DIM;
#pragma unroll
            for (int nt = 0; nt < 16; nt++) {
                int c = nt * 8 + qc;
                float bb0 = sBb[c], bb1 = sBb[c + 1];
                *(float2*)(ob0 + (size_t)qr * DIM + c) =
                    make_float2(acc0[nt][0] + bb0, acc0[nt][1] + bb1);
                *(float2*)(ob0 + (size_t)(qr + 8) * DIM + c) =
                    make_float2(acc0[nt][2] + bb0, acc0[nt][3] + bb1);
                *(float2*)(ob1 + (size_t)qr * DIM + c) =
                    make_float2(acc1[nt][0] + bb0, acc1[nt][1] + bb1);
                *(float2*)(ob1 + (size_t)(qr + 8) * DIM + c) =
                    make_float2(acc1[nt][2] + bb0, acc1[nt][3] + bb1);
            }
        }
        jj = jjn;
    }
}

// ---------------- launch ----------------
extern "C" void kernel_launch(void* const* d_in, const int* in_sizes, int n_in,
                              void* d_out, int out_size) {
    const float* xyz = (const float*)d_in[0];
    const int*   knn = (const int*)d_in[1];
    const float* W1  = (const float*)d_in[2];
    const float* b1  = (const float*)d_in[3];
    const float* W2  = (const float*)d_in[4];
    const float* b2  = (const float*)d_in[5];
    const float* W3a = (const float*)d_in[6];
    const float* b3a = (const float*)d_in[7];
    const float* W3b = (const float*)d_in[8];
    const float* b3b = (const float*)d_in[9];
    float* out = (float*)d_out;

    k_p01<<<NPTS / 16, 256>>>(xyz, W1, b1, W2, b2);

    cudaFuncSetAttribute(k_uc, cudaFuncAttributeMaxDynamicSharedMemorySize, UC_SMEM_BYTES);
    k_uc<<<NPTS / 16, 256, UC_SMEM_BYTES>>>(knn, W3a, b3a);

    cudaFuncSetAttribute(k_mlp, cudaFuncAttributeMaxDynamicSharedMemorySize, SMEM_BYTES);
    int dev = 0, sms = 148;
    cudaGetDevice(&dev);
    cudaDeviceGetAttribute(&sms, cudaDevAttrMultiProcessorCount, dev);
    k_mlp<<<sms, 256, SMEM_BYTES>>>(knn, W3b, b3b, out);
}

// round 13
// speedup vs baseline: 1.0996x; 1.0996x over previous
#include <cuda_runtime.h>
#include <cuda_bf16.h>
#include <cstdint>
#include <math.h>

#define NPTS 50000
#define KNB  16
#define HALF 64
#define DIM  128
#define TILES8 (NPTS / 8)        // 6250
#define RSF   144                // W smem row stride in floats (128 + 16 pad)

// ---------------- scratch (__device__ globals; no allocs allowed) -------
__device__ float g_p0[NPTS * HALF];
__device__ float g_p1[NPTS * HALF];
__device__ float g_u [NPTS * DIM];   // p1 @ W3a_top
__device__ float g_cc[NPTS * DIM];   // b3a - u + p_local @ W3a_bot

// ---------------- k_mlp smem map (bytes) ----------------
#define OFF_WB 0                 // 128 * 144 * 4 = 73728
#define OFF_BB 73728             // 512
#define SMEM_BYTES 74240

#define UC_SMEM_BYTES 75264

// ---------------- helpers ----------------
static __device__ __forceinline__ uint32_t smem_to_u32(const void* p) {
    uint32_t a;
    asm("{ .reg .u64 t; cvta.to.shared.u64 t, %1; cvt.u32.u64 %0, t; }" : "=r"(a) : "l"(p));
    return a;
}
static __device__ __forceinline__ void mma_tf32(float* d,
    uint32_t a0, uint32_t a1, uint32_t a2, uint32_t a3, uint32_t b0, uint32_t b1) {
    asm volatile("mma.sync.aligned.m16n8k8.row.col.f32.tf32.tf32.f32 "
        "{%0,%1,%2,%3}, {%4,%5,%6,%7}, {%8,%9}, {%0,%1,%2,%3};"
        : "+f"(d[0]), "+f"(d[1]), "+f"(d[2]), "+f"(d[3])
        : "r"(a0), "r"(a1), "r"(a2), "r"(a3), "r"(b0), "r"(b1));
}
static __device__ __forceinline__ uint32_t to_tf32(float x) {
    uint32_t r;
    asm("cvt.rna.tf32.f32 %0, %1;" : "=r"(r) : "f"(x));
    return r;
}
// branch-free gelu via A&S 7.1.26 erfc (|eps| <= 1.5e-7), 2 MUFU
static __device__ __forceinline__ float gelu_fast(float x) {
    const float za = fabsf(x) * 0.70710678118654752f;
    float den = fmaf(za, 0.3275911f, 1.0f);
    float t;
    asm("rcp.approx.f32 %0, %1;" : "=f"(t) : "f"(den));
    float q = t * fmaf(t, fmaf(t, fmaf(t, fmaf(t, 0.5307027145f, -0.7265760135f),
                                       0.7107068705f), -0.142248368f), 0.127414796f);
    float ex;
    asm("ex2.approx.f32 %0, %1;" : "=f"(ex) : "f"(za * za * -1.442695041f));
    float E  = q * ex;
    float xe = x * E;
    return (x >= 0.f) ? (x - xe) : xe;
}

// ---------------- kernel 1: p0 = xyz@W1+b1 ; p1 = p0@W2+b2 ----------------
__global__ void __launch_bounds__(256)
k_p01(const float* __restrict__ xyz, const float* __restrict__ W1,
      const float* __restrict__ b1, const float* __restrict__ W2,
      const float* __restrict__ b2) {
    __shared__ float sp0[16][HALF];
    const int tid  = threadIdx.x;
    const int base = blockIdx.x * 16;

    for (int t = tid; t < 16 * HALF; t += 256) {
        int p = t >> 6, c = t & 63;
        int i = base + p;
        float x = __ldg(&xyz[i * 3 + 0]);
        float y = __ldg(&xyz[i * 3 + 1]);
        float z = __ldg(&xyz[i * 3 + 2]);
        float v = fmaf(z, __ldg(&W1[2 * HALF + c]), __ldg(&b1[c]));
        v = fmaf(y, __ldg(&W1[1 * HALF + c]), v);
        v = fmaf(x, __ldg(&W1[0 * HALF + c]), v);
        g_p0[i * HALF + c] = v;
        sp0[p][c] = v;
    }
    __syncthreads();

    const int c  = tid & 63;
    const int p0i = (tid >> 6) * 4;
    float bb = __ldg(&b2[c]);
    float a0 = bb, a1 = bb, a2 = bb, a3 = bb;
#pragma unroll 8
    for (int e = 0; e < HALF; e++) {
        float w = __ldg(&W2[e * HALF + c]);
        a0 = fmaf(sp0[p0i + 0][e], w, a0);
        a1 = fmaf(sp0[p0i + 1][e], w, a1);
        a2 = fmaf(sp0[p0i + 2][e], w, a2);
        a3 = fmaf(sp0[p0i + 3][e], w, a3);
    }
    g_p1[(base + p0i + 0) * HALF + c] = a0;
    g_p1[(base + p0i + 1) * HALF + c] = a1;
    g_p1[(base + p0i + 2) * HALF + c] = a2;
    g_p1[(base + p0i + 3) * HALF + c] = a3;
}

// ---------------- kernel 2: fused p_local + (u, cc) --------------------
__global__ void __launch_bounds__(256)
k_uc(const int* __restrict__ knn, const float* __restrict__ W3a,
     const float* __restrict__ b3a) {
    extern __shared__ float us[];
    float* sW   = us;              // 16384
    float* sp1  = us + 16384;      // 16 x 64
    float* spl  = sp1 + 1024;      // 16 x 64
    float* sb   = spl + 1024;      // 128
    int*   sknn = (int*)(sb + 128);// 256

    const int tid  = threadIdx.x;
    const int base = blockIdx.x * 16;

    for (int t = tid; t < 16384; t += 256) sW[t] = __ldg(&W3a[t]);
    if (tid < 128) sb[tid] = __ldg(&b3a[tid]);
    sknn[tid] = __ldg(&knn[base * KNB + tid]);
    for (int t = tid; t < 1024; t += 256) {
        int p = t >> 6, e = t & 63;
        sp1[t] = g_p1[(base + p) * HALF + e];
    }
    __syncthreads();

    for (int t = tid; t < 1024; t += 256) {
        int p = t >> 6, c = t & 63;
        float own = g_p0[(base + p) * HALF + c];
        float m = -3.402823466e38f;
#pragma unroll
        for (int k = 0; k < KNB; k++) {
            int j = sknn[p * KNB + k];
            m = fmaxf(m, __ldg(&g_p0[j * HALF + c]) - own);
        }
        spl[t] = m;
    }
    __syncthreads();

    const int c  = tid & 127;
    const int ph = (tid >> 7) * 8;
    float aU[8], aC[8];
#pragma unroll
    for (int pp = 0; pp < 8; pp++) { aU[pp] = 0.f; aC[pp] = sb[c]; }
#pragma unroll 8
    for (int e = 0; e < HALF; e++) {
        float w1 = sW[e * DIM + c];
        float w2 = sW[(HALF + e) * DIM + c];
#pragma unroll
        for (int pp = 0; pp < 8; pp++) {
            aU[pp] = fmaf(sp1[(ph + pp) * HALF + e], w1, aU[pp]);
            aC[pp] = fmaf(spl[(ph + pp) * HALF + e], w2, aC[pp]);
        }
    }
#pragma unroll
    for (int pp = 0; pp < 8; pp++) {
        size_t idx = (size_t)(base + ph + pp) * DIM + c;
        g_u[idx]  = aU[pp];
        g_cc[idx] = aC[pp] - aU[pp];
    }
}

// ---------------- kernel 3: gather+GELU -> tf32 GEMM2 --------------------
// Warp owns one point's 16 rows. Single tf32 product (both operands tf32,
// combined error ~3e-4 << 1e-3). W3b stored [n][k] tf32-rounded fp32; each
// lane's B for both k8 chunks of a k16 step is one float4.
__global__ void __launch_bounds__(256, 2)
k_mlp(const int* __restrict__ knn,
      const float* __restrict__ W3b, const float* __restrict__ b3b,
      float* __restrict__ out) {
    extern __shared__ char smem[];
    float* sW  = (float*)(smem + OFF_WB);
    float* sBb = (float*)(smem + OFF_BB);
    const int tid  = threadIdx.x;
    const int wid  = tid >> 5;
    const int lane = tid & 31;

    // ---- load W3b transposed, tf32-rounded: sW[n*RSF + k] = tf32(W3b[k][n])
    for (int idx = tid; idx < 16384; idx += 256) {
        int k = idx >> 7, n = idx & 127;
        uint32_t v = to_tf32(__ldg(&W3b[k * DIM + n]));
        sW[n * RSF + k] = __uint_as_float(v);
    }
    if (tid < 128) sBb[tid] = __ldg(&b3b[tid]);
    __syncthreads();

    const int qr = lane >> 2;            // fragment row group g (0..7)
    const int qc = (lane & 3) * 2;       // output col pair in n8-tile
    const int q4 = (lane & 3) * 4;       // contiguous k base (4c)
    const float* wB = sW + (size_t)qr * RSF + q4;   // + nt*8*RSF + ks*16

    const int gstep = gridDim.x;
    int tile = blockIdx.x;
    if (tile >= TILES8) return;

    // ---- prologue: indices + ks0 data for the first tile ----
    int jj = __ldg(&knn[(tile * 8 + wid) * KNB + (lane & 15)]);
    const float* u0;
    const float* u1;
    const float* cp;
    {
        const int j0 = __shfl_sync(0xFFFFFFFF, jj, qr);
        const int j1 = __shfl_sync(0xFFFFFFFF, jj, qr + 8);
        u0 = g_u  + (size_t)j0 * DIM + q4;
        u1 = g_u  + (size_t)j1 * DIM + q4;
        cp = g_cc + (size_t)(tile * 8 + wid) * DIM + q4;
    }
    float4 va = *(const float4*)(u0);
    float4 vb = *(const float4*)(u1);
    float4 vc = *(const float4*)(cp);

    for (; tile < TILES8; tile += gstep) {
        const int i = tile * 8 + wid;

        const int tnext = tile + gstep;
        int jjn = 0;
        if (tnext < TILES8) jjn = __ldg(&knn[(tnext * 8 + wid) * KNB + (lane & 15)]);

        float acc[16][4];
#pragma unroll
        for (int t = 0; t < 16; t++) { acc[t][0] = acc[t][1] = acc[t][2] = acc[t][3] = 0.f; }

#pragma unroll
        for (int ks = 0; ks < 8; ks++) {
            float4 na, nb, nc;
            if (ks < 7) {
                const int kb = (ks + 1) * 16;
                na = *(const float4*)(u0 + kb);
                nb = *(const float4*)(u1 + kb);
                nc = *(const float4*)(cp + kb);
            } else {
                const int j0n = __shfl_sync(0xFFFFFFFF, jjn, qr);
                const int j1n = __shfl_sync(0xFFFFFFFF, jjn, qr + 8);
                const int inext = (tnext < TILES8) ? (tnext * 8 + wid) : 0;
                u0 = g_u  + (size_t)j0n * DIM + q4;
                u1 = g_u  + (size_t)j1n * DIM + q4;
                cp = g_cc + (size_t)inext * DIM + q4;
                na = *(const float4*)(u0);
                nb = *(const float4*)(u1);
                nc = *(const float4*)(cp);
            }

            // h = gelu(u + cc) for data-k {4c..4c+3}, rows j0 / j1
            uint32_t a00 = to_tf32(gelu_fast(va.x + vc.x));
            uint32_t a01 = to_tf32(gelu_fast(va.y + vc.y));
            uint32_t a02 = to_tf32(gelu_fast(va.z + vc.z));
            uint32_t a03 = to_tf32(gelu_fast(va.w + vc.w));
            uint32_t a10 = to_tf32(gelu_fast(vb.x + vc.x));
            uint32_t a11 = to_tf32(gelu_fast(vb.y + vc.y));
            uint32_t a12 = to_tf32(gelu_fast(vb.z + vc.z));
            uint32_t a13 = to_tf32(gelu_fast(vb.w + vc.w));

            const float* wk = wB + ks * 16;
#pragma unroll
            for (int nt = 0; nt < 16; nt++) {
                float4 w = *(const float4*)(wk + (size_t)nt * 8 * RSF);
                // chunk0: slots {c,c+4} = data {4c,4c+1}
                mma_tf32(acc[nt], a00, a10, a01, a11,
                         __float_as_uint(w.x), __float_as_uint(w.y));
                // chunk1: data {4c+2,4c+3}
                mma_tf32(acc[nt], a02, a12, a03, a13,
                         __float_as_uint(w.z), __float_as_uint(w.w));
            }
            va = na; vb = nb; vc = nc;
        }

        // ---- epilogue: +b3b, store ----
        {
            float* obase = out + ((size_t)i * KNB) * DIM;
#pragma unroll
            for (int nt = 0; nt < 16; nt++) {
                int c = nt * 8 + qc;
                float bb0 = sBb[c], bb1 = sBb[c + 1];
                *(float2*)(obase + (size_t)qr * DIM + c) =
                    make_float2(acc[nt][0] + bb0, acc[nt][1] + bb1);
                *(float2*)(obase + (size_t)(qr + 8) * DIM + c) =
                    make_float2(acc[nt][2] + bb0, acc[nt][3] + bb1);
            }
        }
        jj = jjn;
    }
}

// ---------------- launch ----------------
extern "C" void kernel_launch(void* const* d_in, const int* in_sizes, int n_in,
                              void* d_out, int out_size) {
    const float* xyz = (const float*)d_in[0];
    const int*   knn = (const int*)d_in[1];
    const float* W1  = (const float*)d_in[2];
    const float* b1  = (const float*)d_in[3];
    const float* W2  = (const float*)d_in[4];
    const float* b2  = (const float*)d_in[5];
    const float* W3a = (const float*)d_in[6];
    const float* b3a = (const float*)d_in[7];
    const float* W3b = (const float*)d_in[8];
    const float* b3b = (const float*)d_in[9];
    float* out = (float*)d_out;

    k_p01<<<NPTS / 16, 256>>>(xyz, W1, b1, W2, b2);

    cudaFuncSetAttribute(k_uc, cudaFuncAttributeMaxDynamicSharedMemorySize, UC_SMEM_BYTES);
    k_uc<<<NPTS / 16, 256, UC_SMEM_BYTES>>>(knn, W3a, b3a);

    cudaFuncSetAttribute(k_mlp, cudaFuncAttributeMaxDynamicSharedMemorySize, SMEM_BYTES);
    int dev = 0, sms = 148;
    cudaGetDevice(&dev);
    cudaDeviceGetAttribute(&sms, cudaDevAttrMultiProcessorCount, dev);
    k_mlp<<<2 * sms, 256, SMEM_BYTES>>>(knn, W3b, b3b, out);
}

// round 14
// speedup vs baseline: 1.1125x; 1.0118x over previous
#include <cuda_runtime.h>
#include <cuda_bf16.h>
#include <cstdint>
#include <math.h>

#define NPTS 50000
#define KNB  16
#define HALF 64
#define DIM  128
#define TILES8 (NPTS / 8)        // 6250
#define RSF   144                // W smem row stride in floats (128 + 16 pad)

// ---------------- scratch (__device__ globals; no allocs allowed) -------
__device__ float g_p0[NPTS * HALF];
__device__ float g_p1[NPTS * HALF];
__device__ float g_u [NPTS * DIM];   // p1 @ W3a_top
__device__ float g_cc[NPTS * DIM];   // b3a - u + p_local @ W3a_bot

// ---------------- k_mlp smem map (bytes) ----------------
#define OFF_WB 0                 // 128 * 144 * 4 = 73728
#define OFF_BB 73728             // 512
#define SMEM_BYTES 74240

#define UC_SMEM_BYTES 75264

// ---------------- helpers ----------------
static __device__ __forceinline__ void mma_tf32(float* d,
    uint32_t a0, uint32_t a1, uint32_t a2, uint32_t a3, uint32_t b0, uint32_t b1) {
    asm volatile("mma.sync.aligned.m16n8k8.row.col.f32.tf32.tf32.f32 "
        "{%0,%1,%2,%3}, {%4,%5,%6,%7}, {%8,%9}, {%0,%1,%2,%3};"
        : "+f"(d[0]), "+f"(d[1]), "+f"(d[2]), "+f"(d[3])
        : "r"(a0), "r"(a1), "r"(a2), "r"(a3), "r"(b0), "r"(b1));
}
static __device__ __forceinline__ uint32_t to_tf32(float x) {
    uint32_t r;
    asm("cvt.rna.tf32.f32 %0, %1;" : "=r"(r) : "f"(x));
    return r;
}
// branch-free gelu via A&S 7.1.26 erfc, constants pre-folded (|eps|<=1.5e-7)
static __device__ __forceinline__ float gelu_fast(float x) {
    float x2 = x * x;
    float den = fmaf(fabsf(x), 0.23173867f, 1.0f);   // p/sqrt(2)
    float t;
    asm("rcp.approx.f32 %0, %1;" : "=f"(t) : "f"(den));
    float q = t * fmaf(t, fmaf(t, fmaf(t, fmaf(t, 0.5307027145f, -0.7265760135f),
                                       0.7107068705f), -0.142248368f), 0.127414796f);
    float ex;
    asm("ex2.approx.f32 %0, %1;" : "=f"(ex) : "f"(x2 * -0.72134752f));  // -1/(2 ln2)
    float E  = q * ex;           // 0.5*erfc(|x|/sqrt2)
    float xe = x * E;
    return (x >= 0.f) ? (x - xe) : xe;
}

// ---------------- kernel 1: p0 = xyz@W1+b1 ; p1 = p0@W2+b2 ----------------
__global__ void __launch_bounds__(256)
k_p01(const float* __restrict__ xyz, const float* __restrict__ W1,
      const float* __restrict__ b1, const float* __restrict__ W2,
      const float* __restrict__ b2) {
    __shared__ float sp0[16][HALF];
    const int tid  = threadIdx.x;
    const int base = blockIdx.x * 16;

    for (int t = tid; t < 16 * HALF; t += 256) {
        int p = t >> 6, c = t & 63;
        int i = base + p;
        float x = __ldg(&xyz[i * 3 + 0]);
        float y = __ldg(&xyz[i * 3 + 1]);
        float z = __ldg(&xyz[i * 3 + 2]);
        float v = fmaf(z, __ldg(&W1[2 * HALF + c]), __ldg(&b1[c]));
        v = fmaf(y, __ldg(&W1[1 * HALF + c]), v);
        v = fmaf(x, __ldg(&W1[0 * HALF + c]), v);
        g_p0[i * HALF + c] = v;
        sp0[p][c] = v;
    }
    __syncthreads();

    const int c  = tid & 63;
    const int p0i = (tid >> 6) * 4;
    float bb = __ldg(&b2[c]);
    float a0 = bb, a1 = bb, a2 = bb, a3 = bb;
#pragma unroll 8
    for (int e = 0; e < HALF; e++) {
        float w = __ldg(&W2[e * HALF + c]);
        a0 = fmaf(sp0[p0i + 0][e], w, a0);
        a1 = fmaf(sp0[p0i + 1][e], w, a1);
        a2 = fmaf(sp0[p0i + 2][e], w, a2);
        a3 = fmaf(sp0[p0i + 3][e], w, a3);
    }
    g_p1[(base + p0i + 0) * HALF + c] = a0;
    g_p1[(base + p0i + 1) * HALF + c] = a1;
    g_p1[(base + p0i + 2) * HALF + c] = a2;
    g_p1[(base + p0i + 3) * HALF + c] = a3;
}

// ---------------- kernel 2: fused p_local + (u, cc) --------------------
// PDL: W3a/b3a/knn staging overlaps k_p01's tail; grid-dep sync before
// any g_p0/g_p1 read.
__global__ void __launch_bounds__(256)
k_uc(const int* __restrict__ knn, const float* __restrict__ W3a,
     const float* __restrict__ b3a) {
    extern __shared__ float us[];
    float* sW   = us;              // 16384
    float* sp1  = us + 16384;      // 16 x 64
    float* spl  = sp1 + 1024;      // 16 x 64
    float* sb   = spl + 1024;      // 128
    int*   sknn = (int*)(sb + 128);// 256

    const int tid  = threadIdx.x;
    const int base = blockIdx.x * 16;

    // prologue: inputs only (runs under PDL overlap)
    for (int t = tid; t < 16384; t += 256) sW[t] = __ldg(&W3a[t]);
    if (tid < 128) sb[tid] = __ldg(&b3a[tid]);
    sknn[tid] = __ldg(&knn[base * KNB + tid]);

    cudaGridDependencySynchronize();   // wait for k_p01's writes

    for (int t = tid; t < 1024; t += 256) {
        int p = t >> 6, e = t & 63;
        sp1[t] = g_p1[(base + p) * HALF + e];
    }
    __syncthreads();

    for (int t = tid; t < 1024; t += 256) {
        int p = t >> 6, c = t & 63;
        float own = g_p0[(base + p) * HALF + c];
        float m = -3.402823466e38f;
#pragma unroll
        for (int k = 0; k < KNB; k++) {
            int j = sknn[p * KNB + k];
            m = fmaxf(m, __ldg(&g_p0[j * HALF + c]) - own);
        }
        spl[t] = m;
    }
    __syncthreads();

    const int c  = tid & 127;
    const int ph = (tid >> 7) * 8;
    float aU[8], aC[8];
#pragma unroll
    for (int pp = 0; pp < 8; pp++) { aU[pp] = 0.f; aC[pp] = sb[c]; }
#pragma unroll 8
    for (int e = 0; e < HALF; e++) {
        float w1 = sW[e * DIM + c];
        float w2 = sW[(HALF + e) * DIM + c];
#pragma unroll
        for (int pp = 0; pp < 8; pp++) {
            aU[pp] = fmaf(sp1[(ph + pp) * HALF + e], w1, aU[pp]);
            aC[pp] = fmaf(spl[(ph + pp) * HALF + e], w2, aC[pp]);
        }
    }
#pragma unroll
    for (int pp = 0; pp < 8; pp++) {
        size_t idx = (size_t)(base + ph + pp) * DIM + c;
        g_u[idx]  = aU[pp];
        g_cc[idx] = aC[pp] - aU[pp];
    }
}

// ---------------- kernel 3: gather+GELU -> tf32 GEMM2 --------------------
// PDL: W3b transpose prologue overlaps k_uc's tail; grid-dep sync before
// any g_u/g_cc read.
__global__ void __launch_bounds__(256, 2)
k_mlp(const int* __restrict__ knn,
      const float* __restrict__ W3b, const float* __restrict__ b3b,
      float* __restrict__ out) {
    extern __shared__ char smem[];
    float* sW  = (float*)(smem + OFF_WB);
    float* sBb = (float*)(smem + OFF_BB);
    const int tid  = threadIdx.x;
    const int wid  = tid >> 5;
    const int lane = tid & 31;

    // prologue: inputs only (runs under PDL overlap)
    for (int idx = tid; idx < 16384; idx += 256) {
        int k = idx >> 7, n = idx & 127;
        uint32_t v = to_tf32(__ldg(&W3b[k * DIM + n]));
        sW[n * RSF + k] = __uint_as_float(v);
    }
    if (tid < 128) sBb[tid] = __ldg(&b3b[tid]);
    __syncthreads();

    const int qr = lane >> 2;            // fragment row group (0..7)
    const int qc = (lane & 3) * 2;       // output col pair in n8-tile
    const int q4 = (lane & 3) * 4;       // contiguous k base
    const float* wB = sW + (size_t)qr * RSF + q4;

    const int gstep = gridDim.x;
    int tile = blockIdx.x;
    if (tile >= TILES8) { cudaGridDependencySynchronize(); return; }

    int jj = __ldg(&knn[(tile * 8 + wid) * KNB + (lane & 15)]);

    cudaGridDependencySynchronize();     // wait for k_uc's g_u/g_cc writes

    const float* u0;
    const float* u1;
    const float* cp;
    {
        const int j0 = __shfl_sync(0xFFFFFFFF, jj, qr);
        const int j1 = __shfl_sync(0xFFFFFFFF, jj, qr + 8);
        u0 = g_u  + (size_t)j0 * DIM + q4;
        u1 = g_u  + (size_t)j1 * DIM + q4;
        cp = g_cc + (size_t)(tile * 8 + wid) * DIM + q4;
    }
    float4 va = *(const float4*)(u0);
    float4 vb = *(const float4*)(u1);
    float4 vc = *(const float4*)(cp);

    for (; tile < TILES8; tile += gstep) {
        const int i = tile * 8 + wid;

        const int tnext = tile + gstep;
        int jjn = 0;
        if (tnext < TILES8) jjn = __ldg(&knn[(tnext * 8 + wid) * KNB + (lane & 15)]);

        float acc[16][4];
#pragma unroll
        for (int t = 0; t < 16; t++) { acc[t][0] = acc[t][1] = acc[t][2] = acc[t][3] = 0.f; }

#pragma unroll
        for (int ks = 0; ks < 8; ks++) {
            float4 na, nb, nc;
            if (ks < 7) {
                const int kb = (ks + 1) * 16;
                na = *(const float4*)(u0 + kb);
                nb = *(const float4*)(u1 + kb);
                nc = *(const float4*)(cp + kb);
            } else {
                const int j0n = __shfl_sync(0xFFFFFFFF, jjn, qr);
                const int j1n = __shfl_sync(0xFFFFFFFF, jjn, qr + 8);
                const int inext = (tnext < TILES8) ? (tnext * 8 + wid) : 0;
                u0 = g_u  + (size_t)j0n * DIM + q4;
                u1 = g_u  + (size_t)j1n * DIM + q4;
                cp = g_cc + (size_t)inext * DIM + q4;
                na = *(const float4*)(u0);
                nb = *(const float4*)(u1);
                nc = *(const float4*)(cp);
            }

            // h = gelu(u + cc) for data-k {4c..4c+3}, rows j0 / j1
            uint32_t a00 = to_tf32(gelu_fast(va.x + vc.x));
            uint32_t a01 = to_tf32(gelu_fast(va.y + vc.y));
            uint32_t a02 = to_tf32(gelu_fast(va.z + vc.z));
            uint32_t a03 = to_tf32(gelu_fast(va.w + vc.w));
            uint32_t a10 = to_tf32(gelu_fast(vb.x + vc.x));
            uint32_t a11 = to_tf32(gelu_fast(vb.y + vc.y));
            uint32_t a12 = to_tf32(gelu_fast(vb.z + vc.z));
            uint32_t a13 = to_tf32(gelu_fast(vb.w + vc.w));

            const float* wk = wB + ks * 16;
#pragma unroll
            for (int nt = 0; nt < 16; nt++) {
                float4 w = *(const float4*)(wk + (size_t)nt * 8 * RSF);
                mma_tf32(acc[nt], a00, a10, a01, a11,
                         __float_as_uint(w.x), __float_as_uint(w.y));
                mma_tf32(acc[nt], a02, a12, a03, a13,
                         __float_as_uint(w.z), __float_as_uint(w.w));
            }
            va = na; vb = nb; vc = nc;
        }

        // ---- epilogue: +b3b, store ----
        {
            float* obase = out + ((size_t)i * KNB) * DIM;
#pragma unroll
            for (int nt = 0; nt < 16; nt++) {
                int c = nt * 8 + qc;
                float bb0 = sBb[c], bb1 = sBb[c + 1];
                *(float2*)(obase + (size_t)qr * DIM + c) =
                    make_float2(acc[nt][0] + bb0, acc[nt][1] + bb1);
                *(float2*)(obase + (size_t)(qr + 8) * DIM + c) =
                    make_float2(acc[nt][2] + bb0, acc[nt][3] + bb1);
            }
        }
        jj = jjn;
    }
}

// ---------------- launch ----------------
extern "C" void kernel_launch(void* const* d_in, const int* in_sizes, int n_in,
                              void* d_out, int out_size) {
    const float* xyz = (const float*)d_in[0];
    const int*   knn = (const int*)d_in[1];
    const float* W1  = (const float*)d_in[2];
    const float* b1  = (const float*)d_in[3];
    const float* W2  = (const float*)d_in[4];
    const float* b2  = (const float*)d_in[5];
    const float* W3a = (const float*)d_in[6];
    const float* b3a = (const float*)d_in[7];
    const float* W3b = (const float*)d_in[8];
    const float* b3b = (const float*)d_in[9];
    float* out = (float*)d_out;

    cudaFuncSetAttribute(k_uc, cudaFuncAttributeMaxDynamicSharedMemorySize, UC_SMEM_BYTES);
    cudaFuncSetAttribute(k_mlp, cudaFuncAttributeMaxDynamicSharedMemorySize, SMEM_BYTES);

    int dev = 0, sms = 148;
    cudaGetDevice(&dev);
    cudaDeviceGetAttribute(&sms, cudaDevAttrMultiProcessorCount, dev);

    k_p01<<<NPTS / 16, 256>>>(xyz, W1, b1, W2, b2);

    cudaLaunchAttribute attr[1];
    attr[0].id = cudaLaunchAttributeProgrammaticStreamSerialization;
    attr[0].val.programmaticStreamSerializationAllowed = 1;

    {   // k_uc with PDL (prologue overlaps k_p01 tail)
        cudaLaunchConfig_t cfg = {};
        cfg.gridDim = dim3(NPTS / 16, 1, 1);
        cfg.blockDim = dim3(256, 1, 1);
        cfg.dynamicSmemBytes = UC_SMEM_BYTES;
        cfg.stream = 0;
        cfg.attrs = attr;
        cfg.numAttrs = 1;
        cudaLaunchKernelEx(&cfg, k_uc, knn, W3a, b3a);
    }
    {   // k_mlp with PDL (W transpose overlaps k_uc tail)
        cudaLaunchConfig_t cfg = {};
        cfg.gridDim = dim3(2 * sms, 1, 1);
        cfg.blockDim = dim3(256, 1, 1);
        cfg.dynamicSmemBytes = SMEM_BYTES;
        cfg.stream = 0;
        cfg.attrs = attr;
        cfg.numAttrs = 1;
        cudaLaunchKernelEx(&cfg, k_mlp, knn, W3b, b3b, out);
    }
}